// round 17
// baseline (speedup 1.0000x reference)
#include <cuda_runtime.h>
#include <cuda_fp16.h>
#include <cstdint>

// RBF: out[n] = sum_m w[m]*exp(-dist(n,m)). Screen-then-refine:
//  1) fp16 GEMM (K=576 features) -> approx dist; approx<128 => survivor bit
//     (superset of true dist<100; dist>=100 contributes exact fp32 zero).
//  2) per-n warp refines survivors exactly in fp32 (triangle blob).
// Round 15: flattened 288-chunk cp.async stream (no per-mb ring drains),
// mask words assembled with shfl-OR + plain stores (zero_mask kernel gone),
// prep_a via smem-x + sentinel feature table (half2 stores).

#define DD 32
#define NN 32768
#define MM 2048
#define KS 576
#define KCH 32
#define NCHK 18
#define TOTCH (16 * NCHK)       // 288 flattened chunks
#define NT 64
#define MT 64
#define CSTR 40                 // halfs; conflict-free ldmatrix (20w stride)
#define PLN (64 * CSTR)
#define STB (3 * PLN * 2)       // 15360 B/stage
#define DSMEM (4 * STB)         // 61440
#define TH 128.0f
#define BLOB 640

__device__ __align__(16) __half g_A[(size_t)NN * KS];
__device__ __align__(16) __half g_B[(size_t)MM * KS];
__device__ __align__(16) float g_blob[(size_t)MM * BLOB];
__device__ uint32_t g_mask[(size_t)NN * (MM / 32)];
__device__ int g_tabD[KS];
__device__ int g_tabE[KS];
__device__ int g_rs[DD];

__host__ __device__ constexpr int padlen(int d) { return ((DD - d + 3) / 4) * 4; }
__host__ __device__ constexpr int rowstart(int d) {
    int s = 0;
    for (int k = 0; k < d; k++) s += padlen(k);
    return s;
}

// ---- helpers ---------------------------------------------------------------
__device__ __forceinline__ void mma16816(float* c, const uint32_t* a,
                                         const uint32_t* b) {
    asm("mma.sync.aligned.m16n8k16.row.col.f32.f16.f16.f32 "
        "{%0,%1,%2,%3}, {%4,%5,%6,%7}, {%8,%9}, {%0,%1,%2,%3};"
        : "+f"(c[0]), "+f"(c[1]), "+f"(c[2]), "+f"(c[3])
        : "r"(a[0]), "r"(a[1]), "r"(a[2]), "r"(a[3]), "r"(b[0]), "r"(b[1]));
}
__device__ __forceinline__ void cp16(uint32_t dst, const void* src) {
    asm volatile("cp.async.cg.shared.global [%0], [%1], 16;" ::"r"(dst), "l"(src));
}
#define LDSM4(r, addr)                                                    \
    asm volatile(                                                         \
        "ldmatrix.sync.aligned.m8n8.x4.shared.b16 {%0,%1,%2,%3}, [%4];"   \
        : "=r"((r)[0]), "=r"((r)[1]), "=r"((r)[2]), "=r"((r)[3])          \
        : "r"(addr))

// ---- Kernel 0: index tables (sentinel form: f = xs[d]*xs[e]) ---------------
// k<528: (d,e) triangle. 528+i: (i,32) -> x_i (xs[32]=1). 560: (32,32) -> 1.
// >560: (33,33) -> 0 (xs[33]=0).
__global__ void prep_tri_kernel() {
    int k = threadIdx.x;
    if (k < 528) {
        int d = 0, rem = k;
        while (rem >= DD - d) { rem -= DD - d; d++; }
        g_tabD[k] = d;
        g_tabE[k] = d + rem;
    } else if (k < 560) {
        g_tabD[k] = k - 528;
        g_tabE[k] = 32;
    } else if (k == 560) {
        g_tabD[k] = 32;
        g_tabE[k] = 32;
    } else if (k < KS) {
        g_tabD[k] = 33;
        g_tabE[k] = 33;
    }
    if (k < DD) {
        int s = 0;
        for (int q = 0; q < k; q++) s += padlen(q);
        g_rs[k] = s;
    }
}

// ---- Kernel 1: blob (fp32 triangle/bm2/c) + fp16 B row, fused -------------
__global__ __launch_bounds__(128) void prep_blob_kernel(
    const float* __restrict__ gamma, const float* __restrict__ means) {
    __shared__ float Gs[DD * DD];
    __shared__ float Cs[DD * DD];
    __shared__ float mus[DD];
    __shared__ float bs[DD];

    const int m = blockIdx.x;
    const int tid = threadIdx.x;
    float* blob = g_blob + (size_t)m * BLOB;
    __half* bout = g_B + (size_t)m * KS;

    const float* gsrc = gamma + (size_t)m * DD * DD;
#pragma unroll
    for (int i = tid; i < DD * DD; i += 128) Gs[i] = gsrc[i];
    if (tid < DD) mus[tid] = means[(size_t)m * DD + tid];
    for (int i = tid; i < BLOB; i += 128) blob[i] = 0.0f;
    for (int i = tid; i < KS; i += 128) bout[i] = __float2half_rn(0.0f);
    __syncthreads();

    for (int idx = tid; idx < 528; idx += 128) {
        const int d = g_tabD[idx], e = g_tabE[idx];
        float c = 0.0f;
#pragma unroll
        for (int k = 0; k < DD; k++) c += Gs[d * DD + k] * Gs[e * DD + k];
        Cs[d * DD + e] = c;
        Cs[e * DD + d] = c;
        const float v = (e == d) ? c : 2.0f * c;
        blob[g_rs[d] + (e - d)] = v;
        bout[idx] = __float2half_rn(v);
    }
    __syncthreads();

    if (tid < DD) {
        float b = 0.0f;
#pragma unroll
        for (int e = 0; e < DD; e++) b += Cs[tid * DD + e] * mus[e];
        bs[tid] = b;
        blob[576 + tid] = -2.0f * b;
        bout[528 + tid] = __float2half_rn(-2.0f * b);
    }
    __syncthreads();

    if (tid == 0) {
        float c = 0.0f;
#pragma unroll
        for (int d = 0; d < DD; d++) c += bs[d] * mus[d];
        blob[608] = c;
        bout[560] = __float2half_rn(c);
    }
}

// ---- Kernel 2: A features in fp16 (smem-x, half2 stores) ------------------
__global__ __launch_bounds__(128) void prep_a_kernel(const float* __restrict__ x) {
    __shared__ float xs[4][36];  // [32]=1, [33]=0 sentinels
    const int warp = threadIdx.x / 32, lane = threadIdx.x % 32;
    const int n = blockIdx.x * 4 + warp;

    xs[warp][lane] = x[(size_t)n * DD + lane];
    if (lane == 0) {
        xs[warp][32] = 1.0f;
        xs[warp][33] = 0.0f;
    }
    __syncwarp();

    __half2* o = reinterpret_cast<__half2*>(g_A + (size_t)n * KS);
#pragma unroll
    for (int j = 0; j < KS / 64; j++) {  // 9 iterations, half2 per lane
        const int k = j * 64 + lane * 2;
        const float f0 = xs[warp][__ldg(&g_tabD[k])] * xs[warp][__ldg(&g_tabE[k])];
        const float f1 =
            xs[warp][__ldg(&g_tabD[k + 1])] * xs[warp][__ldg(&g_tabE[k + 1])];
        o[k >> 1] = __floats2half2_rn(f0, f1);
    }
}

// ---- Kernel 3: screening GEMM, flattened chunk stream ---------------------
__global__ __launch_bounds__(256, 3) void screen_kernel() {
    extern __shared__ __align__(16) unsigned char dsm[];
    const int tid = threadIdx.x;
    const int warp = tid >> 5, lane = tid & 31;
    const int wg = warp & 3;   // row group
    const int wh = warp >> 2;  // m half
    const int n0 = blockIdx.x * NT;
    const uint32_t smem = (uint32_t)__cvta_generic_to_shared(dsm);

    const int rloc = lane & 7;
    const uint32_t a_off =
        (uint32_t)(((wg * 16 + ((lane >> 3) & 1) * 8 + rloc) * CSTR +
                    ((lane >> 4) & 1) * 8) * 2);
    const uint32_t b_off =
        (uint32_t)(((((lane >> 4) & 1) * 8 + rloc) * CSTR + ((lane >> 3) & 1) * 8) * 2);
    const uint32_t b_plane = (uint32_t)((1 + wh) * PLN * 2);

    // flat chunk t -> (mb = t/NCHK, ch = t%NCHK)
    auto issue = [&](int t) {
        const int mb_i = t / NCHK;
        const int ko = (t - mb_i * NCHK) * KCH;
        const uint32_t stg = smem + (t & 3) * STB;
#pragma unroll
        for (int q = 0; q < 3; q++) {
            const int unit = tid + 256 * q;
            const int plane = unit >> 8;  // 0:A 1:B(lo half) 2:B(hi half)
            const int row = (unit & 255) >> 2, h = unit & 3;
            const uint32_t dst = stg + (uint32_t)(plane * PLN * 2) +
                                 (uint32_t)((row * CSTR + h * 8) * 2);
            const __half* src =
                (plane == 0)
                    ? g_A + (size_t)(n0 + row) * KS + ko + h * 8
                    : g_B + (size_t)(((mb_i + (plane - 1) * 16) * MT) + row) * KS + ko + h * 8;
            cp16(dst, src);
        }
        asm volatile("cp.async.commit_group;");
    };

    issue(0);
    issue(1);
    issue(2);

    float c[8][4];
#pragma unroll
    for (int j = 0; j < 8; j++) {
        c[j][0] = 0.0f; c[j][1] = 0.0f; c[j][2] = 0.0f; c[j][3] = 0.0f;
    }

    int mb = 0, ch = 0;
    for (int t = 0; t < TOTCH; t++) {
        if (t < TOTCH - 2) asm volatile("cp.async.wait_group 2;");
        else if (t == TOTCH - 2) asm volatile("cp.async.wait_group 1;");
        else asm volatile("cp.async.wait_group 0;");
        __syncthreads();
        if (t + 3 < TOTCH) issue(t + 3);

        const uint32_t stg = smem + (t & 3) * STB;

#pragma unroll
        for (int kst = 0; kst < 2; kst++) {
            uint32_t afr[4];
            LDSM4(afr, stg + a_off + (uint32_t)(kst * 32));
            uint32_t bfr[4][4];
#pragma unroll
            for (int u = 0; u < 4; u++)
                LDSM4(bfr[u], stg + b_plane + b_off +
                                  (uint32_t)(u * 16 * CSTR * 2 + kst * 32));
#pragma unroll
            for (int u = 0; u < 4; u++) {
                mma16816(c[2 * u], afr, &bfr[u][0]);
                mma16816(c[2 * u + 1], afr, &bfr[u][2]);
            }
        }

        if (++ch == NCHK) {
            // epilogue for tile mb: assemble mask words, plain stores
            const int r0 = n0 + wg * 16 + (lane >> 2);
            const int la = lane & 3;
            const int mbe = mb + wh * 16;
#pragma unroll
            for (int w = 0; w < 2; w++) {
                uint32_t m0 = 0, m1 = 0;
#pragma unroll
                for (int jj = 0; jj < 4; jj++) {
                    const int j = w * 4 + jj;
                    if (c[j][0] < TH) m0 |= 1u << (jj * 8 + la * 2);
                    if (c[j][1] < TH) m0 |= 1u << (jj * 8 + la * 2 + 1);
                    if (c[j][2] < TH) m1 |= 1u << (jj * 8 + la * 2);
                    if (c[j][3] < TH) m1 |= 1u << (jj * 8 + la * 2 + 1);
                }
                m0 |= __shfl_xor_sync(0xFFFFFFFFu, m0, 1);
                m0 |= __shfl_xor_sync(0xFFFFFFFFu, m0, 2);
                m1 |= __shfl_xor_sync(0xFFFFFFFFu, m1, 1);
                m1 |= __shfl_xor_sync(0xFFFFFFFFu, m1, 2);
                if (la == 0) {
                    g_mask[(size_t)r0 * 64 + mbe * 2 + w] = m0;
                    g_mask[(size_t)(r0 + 8) * 64 + mbe * 2 + w] = m1;
                }
            }
#pragma unroll
            for (int j = 0; j < 8; j++) {
                c[j][0] = 0.0f; c[j][1] = 0.0f; c[j][2] = 0.0f; c[j][3] = 0.0f;
            }
            ch = 0;
            mb++;
        }
    }
}

// ---- Kernel 4: exact refine of survivors, one warp per n ------------------
__global__ __launch_bounds__(256) void refine_kernel(const float* __restrict__ x,
                                                     const float* __restrict__ w,
                                                     float* __restrict__ out) {
    const int warp = threadIdx.x >> 5, lane = threadIdx.x & 31;
    const int n = blockIdx.x * 8 + warp;

    float xr[DD];
    {
        const float4* xp = reinterpret_cast<const float4*>(x + (size_t)n * DD);
#pragma unroll
        for (int i = 0; i < DD / 4; i++) {
            float4 v = __ldg(xp + i);
            xr[4 * i] = v.x; xr[4 * i + 1] = v.y;
            xr[4 * i + 2] = v.z; xr[4 * i + 3] = v.w;
        }
    }

    float acc = 0.0f;
#pragma unroll 1
    for (int wi = 0; wi < 2; wi++) {
        const int widx = wi * 32 + lane;
        uint32_t word = g_mask[(size_t)n * 64 + widx];
        while (word) {
            const int b = __ffs(word) - 1;
            word &= word - 1;
            const int m = widx * 32 + b;
            const float* blob = g_blob + (size_t)m * BLOB;
            const float4* t4 = reinterpret_cast<const float4*>(blob);

            float dist = __ldg(blob + 608);
#pragma unroll
            for (int d = 0; d < DD; d++) {
                float t0 = 0.0f, t1 = 0.0f, t2 = 0.0f, t3 = 0.0f;
                const int ro4 = rowstart(d) / 4;
#pragma unroll
                for (int g = 0; g < padlen(d) / 4; g++) {
                    float4 v = __ldg(t4 + ro4 + g);
                    const int e0 = d + 4 * g;
                    t0 += v.x * xr[e0];
                    if (e0 + 1 < DD) t1 += v.y * xr[e0 + 1];
                    if (e0 + 2 < DD) t2 += v.z * xr[e0 + 2];
                    if (e0 + 3 < DD) t3 += v.w * xr[e0 + 3];
                }
                dist += xr[d] * ((t0 + t1) + (t2 + t3));
            }
#pragma unroll
            for (int g = 0; g < DD / 4; g++) {
                float4 v = __ldg(t4 + 144 + g);
                dist += v.x * xr[4 * g] + v.y * xr[4 * g + 1] +
                        v.z * xr[4 * g + 2] + v.w * xr[4 * g + 3];
            }
            if (dist < 100.0f) acc += __ldg(w + m) * __expf(-dist);
        }
    }

#pragma unroll
    for (int s = 16; s > 0; s >>= 1) acc += __shfl_xor_sync(0xFFFFFFFFu, acc, s);
    if (lane == 0) out[n] = acc;
}

extern "C" void kernel_launch(void* const* d_in, const int* in_sizes, int n_in,
                              void* d_out, int out_size) {
    const float* inputs = (const float*)d_in[0];   // [N, D]
    const float* gamma = (const float*)d_in[1];    // [M, D, D]
    const float* means = (const float*)d_in[2];    // [M, D]
    const float* weights = (const float*)d_in[3];  // [M]
    float* out = (float*)d_out;                    // [N, 1]

    cudaFuncSetAttribute(screen_kernel, cudaFuncAttributeMaxDynamicSharedMemorySize,
                         DSMEM);

    prep_tri_kernel<<<1, KS>>>();
    prep_blob_kernel<<<MM, 128>>>(gamma, means);
    prep_a_kernel<<<NN / 4, 128>>>(inputs);
    screen_kernel<<<NN / NT, 256, DSMEM>>>();
    refine_kernel<<<NN / 8, 256>>>(inputs, weights, out);
}